// round 11
// baseline (speedup 1.0000x reference)
#include <cuda_runtime.h>
#include <cuda_bf16.h>
#include <math.h>
#include <stdint.h>

#define CIN   128
#define COUT  512
#define NMAX  50000
#define EMAX  800000

// ---------------- scratch (static __device__, no runtime alloc) ----------------
__device__ int   g_cnt[NMAX];
__device__ int   g_rowptr[NMAX + 1];
__device__ int   g_cursor[NMAX];
__device__ int2  g_rec[EMAX];              // {src, bits(dinv[src])}
__device__ float g_dinv[NMAX];
__device__ int   g_bsum[512];
__device__ int   g_is64;
__device__ float g_h0[(size_t)NMAX * CIN];
__device__ unsigned short g_h1hi[(size_t)NMAX * CIN];
__device__ unsigned short g_h1lo[(size_t)NMAX * CIN];
__device__ unsigned short g_whi[COUT * CIN];
__device__ unsigned short g_wlo[COUT * CIN];

// ======================= helpers =======================
__device__ __forceinline__ uint32_t smem_to_u32(const void* p) {
    uint32_t a;
    asm("{ .reg .u64 t; cvta.to.shared.u64 t, %1; cvt.u32.u64 %0, t; }" : "=r"(a) : "l"(p));
    return a;
}
__device__ __forceinline__ unsigned short bfbits(float v) {
    __nv_bfloat16 b = __float2bfloat16(v);
    return *reinterpret_cast<unsigned short*>(&b);
}
__device__ __forceinline__ float bfval(unsigned short u) {
    __nv_bfloat16 b = *reinterpret_cast<__nv_bfloat16*>(&u);
    return __bfloat162float(b);
}
__device__ __forceinline__ void ldm4(uint32_t* r, uint32_t addr) {
    asm volatile("ldmatrix.sync.aligned.m8n8.x4.shared.b16 {%0,%1,%2,%3}, [%4];"
                 : "=r"(r[0]), "=r"(r[1]), "=r"(r[2]), "=r"(r[3]) : "r"(addr));
}
__device__ __forceinline__ void mma16816(float* d, const uint32_t* a, const uint32_t* b) {
    asm volatile(
        "mma.sync.aligned.m16n8k16.row.col.f32.bf16.bf16.f32 "
        "{%0,%1,%2,%3}, {%4,%5,%6,%7}, {%8,%9}, {%0,%1,%2,%3};"
        : "+f"(d[0]), "+f"(d[1]), "+f"(d[2]), "+f"(d[3])
        : "r"(a[0]), "r"(a[1]), "r"(a[2]), "r"(a[3]), "r"(b[0]), "r"(b[1]));
}
__device__ __forceinline__ int edge_at(const void* ei, long long idx, int is64) {
    return is64 ? (int)((const long long*)ei)[idx] : ((const int*)ei)[idx];
}
__device__ __forceinline__ void cpa16(uint32_t dst, const void* src) {
    asm volatile("cp.async.cg.shared.global [%0], [%1], 16;" :: "r"(dst), "l"(src));
}
__device__ __forceinline__ void cpa16z(uint32_t dst, const void* src, int sz) {
    asm volatile("cp.async.cg.shared.global [%0], [%1], 16, %2;" :: "r"(dst), "l"(src), "r"(sz));
}
#define CPA_COMMIT() asm volatile("cp.async.commit_group;" ::: "memory")
#define CPA_WAIT1()  asm volatile("cp.async.wait_group 1;" ::: "memory")
#define CPA_WAIT0()  asm volatile("cp.async.wait_group 0;" ::: "memory")

// ---------------- K1: zero counters + dtype probe + W split ----------------
__global__ void init_kernel(const unsigned int* p, int n_vals, int N, const float* __restrict__ W) {
    int i = blockIdx.x * blockDim.x + threadIdx.x;
    if (i < N) g_cnt[i] = 0;
    if (blockIdx.x == 0) {
        __shared__ int any;
        int t = threadIdx.x;
        if (t == 0) any = 0;
        __syncthreads();
        int samples = n_vals < 512 ? n_vals : 512;
        for (int j = t; j < samples; j += blockDim.x)
            if (p[2 * j + 1] != 0u) any = 1;
        __syncthreads();
        if (t == 0) g_is64 = (any == 0) ? 1 : 0;
    }
    for (int k = i; k < COUT * CIN / 4; k += gridDim.x * blockDim.x) {
        float4 v = ((const float4*)W)[k];
        unsigned short h0 = bfbits(v.x), h1 = bfbits(v.y), h2 = bfbits(v.z), h3 = bfbits(v.w);
        unsigned short l0 = bfbits(v.x - bfval(h0)), l1 = bfbits(v.y - bfval(h1));
        unsigned short l2 = bfbits(v.z - bfval(h2)), l3 = bfbits(v.w - bfval(h3));
        uint2 hp, lp;
        hp.x = (uint32_t)h0 | ((uint32_t)h1 << 16); hp.y = (uint32_t)h2 | ((uint32_t)h3 << 16);
        lp.x = (uint32_t)l0 | ((uint32_t)l1 << 16); lp.y = (uint32_t)l2 | ((uint32_t)l3 << 16);
        ((uint2*)g_whi)[k] = hp;
        ((uint2*)g_wlo)[k] = lp;
    }
}

// ---------------- K2: degree histogram ----------------
__global__ void hist_kernel(const void* ei, int E) {
    int e = blockIdx.x * blockDim.x + threadIdx.x;
    if (e >= E) return;
    int dst = edge_at(ei, (long long)E + e, g_is64);
    atomicAdd(&g_cnt[dst], 1);
}

// ---------------- K3: per-block scan + block sums + dinv ----------------
__global__ void scan1_kernel(int N) {
    __shared__ int sm[256];
    int t = threadIdx.x, i = blockIdx.x * 256 + t;
    int v = (i < N) ? g_cnt[i] : 0;
    sm[t] = v;
    __syncthreads();
    for (int off = 1; off < 256; off <<= 1) {
        int add = (t >= off) ? sm[t - off] : 0;
        __syncthreads();
        sm[t] += add;
        __syncthreads();
    }
    if (i < N) {
        g_rowptr[i] = sm[t] - v;
        g_dinv[i] = rsqrtf((float)(v + 1));
    }
    if (t == 255) g_bsum[blockIdx.x] = sm[255];
}

// ---------------- K4: add block-sum prefix (re-reduced per block) ----------------
__global__ void scan3_kernel(int N) {
    __shared__ int red[256];
    int t = threadIdx.x, bid = blockIdx.x;
    int acc = 0;
    for (int j = t; j < bid; j += 256) acc += g_bsum[j];
    red[t] = acc;
    __syncthreads();
    for (int off = 128; off > 0; off >>= 1) {
        if (t < off) red[t] += red[t + off];
        __syncthreads();
    }
    int base = red[0];
    int i = bid * 256 + t;
    if (i < N) {
        int r = g_rowptr[i] + base;
        g_rowptr[i] = r;
        g_cursor[i] = r;
        if (i == N - 1) g_rowptr[N] = r + g_cnt[i];
    }
}

// ---------------- K5: scatter edges into CSR records ----------------
__global__ void scatter_kernel(const void* ei, int E) {
    int e = blockIdx.x * blockDim.x + threadIdx.x;
    if (e >= E) return;
    int is64 = g_is64;
    int src = edge_at(ei, e, is64);
    int dst = edge_at(ei, (long long)E + e, is64);
    int pos = atomicAdd(&g_cursor[dst], 1);
    int2 r;
    r.x = src;
    r.y = __float_as_int(g_dinv[src]);
    g_rec[pos] = r;
}

// ---------------- aggregation inner (warp per dst, unroll x2) ----------------
__device__ __forceinline__ float4 agg_row(const float4* __restrict__ h4, int w, int lane) {
    float dd = g_dinv[w];
    float4 hv = h4[(size_t)w * 32 + lane];
    float s = dd * dd;
    float ax = s * hv.x, ay = s * hv.y, az = s * hv.z, aw = s * hv.w;
    float bx = 0.f, by = 0.f, bz = 0.f, bw = 0.f;
    int e = g_rowptr[w], end = g_rowptr[w + 1];
    for (; e + 2 <= end; e += 2) {
        int2 r0 = g_rec[e], r1 = g_rec[e + 1];
        float c0 = __int_as_float(r0.y) * dd;
        float c1 = __int_as_float(r1.y) * dd;
        float4 v0 = h4[(size_t)r0.x * 32 + lane];
        float4 v1 = h4[(size_t)r1.x * 32 + lane];
        ax += c0 * v0.x; ay += c0 * v0.y; az += c0 * v0.z; aw += c0 * v0.w;
        bx += c1 * v1.x; by += c1 * v1.y; bz += c1 * v1.z; bw += c1 * v1.w;
    }
    if (e < end) {
        int2 r0 = g_rec[e];
        float c0 = __int_as_float(r0.y) * dd;
        float4 v0 = h4[(size_t)r0.x * 32 + lane];
        ax += c0 * v0.x; ay += c0 * v0.y; az += c0 * v0.z; aw += c0 * v0.w;
    }
    float4 o;
    o.x = ax + bx; o.y = ay + by; o.z = az + bz; o.w = aw + bw;
    return o;
}

// K6: hop 1 -> f32
__global__ void agg_kernel(const float* __restrict__ hin, float* __restrict__ hout, int N) {
    int gt = blockIdx.x * blockDim.x + threadIdx.x;
    int w = gt >> 5, lane = gt & 31;
    if (w >= N) return;
    float4 o = agg_row((const float4*)hin, w, lane);
    ((float4*)hout)[(size_t)w * 32 + lane] = o;
}

// K7: hop 2 -> pre-split bf16 hi/lo
__global__ void agg_split_kernel(const float* __restrict__ hin, int N) {
    int gt = blockIdx.x * blockDim.x + threadIdx.x;
    int w = gt >> 5, lane = gt & 31;
    if (w >= N) return;
    float4 o = agg_row((const float4*)hin, w, lane);
    unsigned short h0 = bfbits(o.x), h1 = bfbits(o.y), h2 = bfbits(o.z), h3 = bfbits(o.w);
    unsigned short l0 = bfbits(o.x - bfval(h0)), l1 = bfbits(o.y - bfval(h1));
    unsigned short l2 = bfbits(o.z - bfval(h2)), l3 = bfbits(o.w - bfval(h3));
    uint2 hp, lp;
    hp.x = (uint32_t)h0 | ((uint32_t)h1 << 16); hp.y = (uint32_t)h2 | ((uint32_t)h3 << 16);
    lp.x = (uint32_t)l0 | ((uint32_t)l1 << 16); lp.y = (uint32_t)l2 | ((uint32_t)l3 << 16);
    ((uint2*)g_h1hi)[(size_t)w * 32 + lane] = hp;
    ((uint2*)g_h1lo)[(size_t)w * 32 + lane] = lp;
}

// ---------------- K8: mma.sync GEMM, 2 CTAs/SM, A-resident, 32-col B steps x16, double-buffered ----------------
#define STRIDE_B 272
#define OFF_AHI  0
#define OFF_ALO  34816
#define OFF_B0   69632
#define OFF_B1   87040
#define BPLANE   8704
#define MM_SMEM  104448

__global__ __launch_bounds__(256, 2) void mm_kernel(
    const float* __restrict__ bias, float* __restrict__ out, int N)
{
    extern __shared__ char smem[];
    const int tid = threadIdx.x;
    const int node0 = blockIdx.x * 128;
    const uint32_t sb = smem_to_u32(smem);

    const uint4* hhi = (const uint4*)g_h1hi;
    const uint4* hlo = (const uint4*)g_h1lo;
    const uint4* whi = (const uint4*)g_whi;
    const uint4* wlo = (const uint4*)g_wlo;

    // ---- prologue: group0 = A (zero-filled OOB) + B step 0; group1 = B step 1 ----
    for (int i = tid; i < 2048; i += 256) {
        int row = i >> 4, q = i & 15;
        int gn = node0 + row;
        int sz = (gn < N) ? 16 : 0;
        int gc = (gn < N) ? gn : 0;
        cpa16z(sb + OFF_AHI + row * STRIDE_B + q * 16, &hhi[(size_t)gc * 16 + q], sz);
        cpa16z(sb + OFF_ALO + row * STRIDE_B + q * 16, &hlo[(size_t)gc * 16 + q], sz);
    }
    for (int i = tid; i < 512; i += 256) {
        int row = i >> 4, q = i & 15;                 // W rows 0..31
        cpa16(sb + OFF_B0 + row * STRIDE_B + q * 16, &whi[(size_t)row * 16 + q]);
        cpa16(sb + OFF_B0 + BPLANE + row * STRIDE_B + q * 16, &wlo[(size_t)row * 16 + q]);
    }
    CPA_COMMIT();
    for (int i = tid; i < 512; i += 256) {
        int row = i >> 4, q = i & 15;                 // W rows 32..63
        cpa16(sb + OFF_B1 + row * STRIDE_B + q * 16, &whi[(size_t)(32 + row) * 16 + q]);
        cpa16(sb + OFF_B1 + BPLANE + row * STRIDE_B + q * 16, &wlo[(size_t)(32 + row) * 16 + q]);
    }
    CPA_COMMIT();

    const int lane = tid & 31, wid = tid >> 5;
    const int m0 = (wid & 3) * 32;          // 4 warps along M
    const int n0 = (wid >> 2) * 16;         // 2 warps along N (within 32-col step)

    const uint32_t aoff = (uint32_t)(m0 + (lane & 15)) * STRIDE_B + ((lane >> 4) << 4);
    const uint32_t boff = (uint32_t)(n0 + ((lane >> 4) << 3) + (lane & 7)) * STRIDE_B
                        + (((lane >> 3) & 1) << 4);
    const int g = lane >> 2, tg = lane & 3;

    const uint32_t aHiB = sb + OFF_AHI + aoff;
    const uint32_t aLoB = sb + OFF_ALO + aoff;

    for (int s = 0; s < 16; s++) {
        if (s < 15) { CPA_WAIT1(); } else { CPA_WAIT0(); }
        __syncthreads();                     // B(s) (and A on s=0) ready

        const uint32_t bufB = sb + ((s & 1) ? OFF_B1 : OFF_B0);
        const uint32_t bHiB = bufB + boff;
        const uint32_t bLoB = bufB + BPLANE + boff;

        float acc[2][2][4];
        #pragma unroll
        for (int a = 0; a < 2; a++)
            #pragma unroll
            for (int b = 0; b < 2; b++)
                #pragma unroll
                for (int c = 0; c < 4; c++) acc[a][b][c] = 0.f;

        #pragma unroll
        for (int ks = 0; ks < 8; ks++) {
            uint32_t aH[2][4], aL[2][4], bH[4], bL[4];
            ldm4(aH[0], aHiB + ks * 32);
            ldm4(aH[1], aHiB + 16 * STRIDE_B + ks * 32);
            ldm4(aL[0], aLoB + ks * 32);
            ldm4(aL[1], aLoB + 16 * STRIDE_B + ks * 32);
            ldm4(bH, bHiB + ks * 32);
            ldm4(bL, bLoB + ks * 32);
            #pragma unroll
            for (int mt = 0; mt < 2; mt++) {
                mma16816(acc[mt][0], aH[mt], bH);
                mma16816(acc[mt][1], aH[mt], bH + 2);
                mma16816(acc[mt][0], aH[mt], bL);
                mma16816(acc[mt][1], aH[mt], bL + 2);
                mma16816(acc[mt][0], aL[mt], bH);
                mma16816(acc[mt][1], aL[mt], bH + 2);
            }
        }
        __syncthreads();                     // all warps done reading B(s)

        // refill B(s)'s buffer with B(s+2); overlaps the epilogue + next step's compute
        if (s < 14) {
            int colr0 = (s + 2) * 32;
            uint32_t nbuf = sb + ((s & 1) ? OFF_B1 : OFF_B0);
            for (int i = tid; i < 512; i += 256) {
                int row = i >> 4, q = i & 15;
                cpa16(nbuf + row * STRIDE_B + q * 16,
                      &whi[(size_t)(colr0 + row) * 16 + q]);
                cpa16(nbuf + BPLANE + row * STRIDE_B + q * 16,
                      &wlo[(size_t)(colr0 + row) * 16 + q]);
            }
            CPA_COMMIT();
        }

        #pragma unroll
        for (int ng = 0; ng < 2; ng++) {
            int col = s * 32 + n0 + ng * 8 + tg * 2;
            float2 bb = *(const float2*)(bias + col);
            #pragma unroll
            for (int mt = 0; mt < 2; mt++) {
                int r0 = node0 + m0 + mt * 16 + g;
                if (r0 < N) {
                    float y0 = acc[mt][ng][0] + bb.x;
                    float y1 = acc[mt][ng][1] + bb.y;
                    float2 o;
                    o.x = (y0 >= 0.f) ? y0 : 0.1f * y0;
                    o.y = (y1 >= 0.f) ? y1 : 0.1f * y1;
                    *(float2*)(out + (size_t)r0 * COUT + col) = o;
                }
                int r1 = r0 + 8;
                if (r1 < N) {
                    float y2 = acc[mt][ng][2] + bb.x;
                    float y3 = acc[mt][ng][3] + bb.y;
                    float2 o;
                    o.x = (y2 >= 0.f) ? y2 : 0.1f * y2;
                    o.y = (y3 >= 0.f) ? y3 : 0.1f * y3;
                    *(float2*)(out + (size_t)r1 * COUT + col) = o;
                }
            }
        }
    }
}

extern "C" void kernel_launch(void* const* d_in, const int* in_sizes, int n_in,
                              void* d_out, int out_size) {
    const float* x  = (const float*)d_in[0];
    const void*  ei = d_in[1];
    const float* W  = (const float*)d_in[2];
    const float* b  = (const float*)d_in[3];
    float* out = (float*)d_out;

    int N = in_sizes[0] / CIN;
    int E = in_sizes[1] / 2;

    void* h0p = nullptr;
    cudaGetSymbolAddress(&h0p, g_h0);

    int nbN = (N + 255) / 256;
    int nbE = (E + 255) / 256;

    init_kernel<<<nbN, 256>>>((const unsigned int*)ei, 2 * E, N, W);
    hist_kernel<<<nbE, 256>>>(ei, E);
    scan1_kernel<<<nbN, 256>>>(N);
    scan3_kernel<<<nbN, 256>>>(N);
    scatter_kernel<<<nbE, 256>>>(ei, E);

    int ab = (N * 32 + 255) / 256;
    agg_kernel<<<ab, 256>>>(x, (float*)h0p, N);
    agg_split_kernel<<<ab, 256>>>((const float*)h0p, N);

    cudaFuncSetAttribute(mm_kernel, cudaFuncAttributeMaxDynamicSharedMemorySize, MM_SMEM);
    mm_kernel<<<(N + 127) / 128, 256, MM_SMEM>>>(b, out, N);
}

// round 12
// speedup vs baseline: 1.0413x; 1.0413x over previous
#include <cuda_runtime.h>
#include <cuda_bf16.h>
#include <math.h>
#include <stdint.h>

#define CIN   128
#define COUT  512
#define NMAX  50000
#define EMAX  800000

// ---------------- scratch (static __device__, no runtime alloc) ----------------
__device__ int   g_cnt[NMAX];
__device__ int   g_rowptr[NMAX + 1];
__device__ int   g_cursor[NMAX];
__device__ int2  g_rec[EMAX];              // {src, bits(dinv[src])}
__device__ float g_dinv[NMAX];
__device__ int   g_bsum[512];
__device__ int   g_is64;
__device__ int   g_scnt;                   // scan barrier counter (reset each call)
__device__ float g_h0[(size_t)NMAX * CIN];
__device__ unsigned short g_h1hi[(size_t)NMAX * CIN];
__device__ unsigned short g_h1lo[(size_t)NMAX * CIN];
__device__ unsigned short g_whi[COUT * CIN];
__device__ unsigned short g_wlo[COUT * CIN];

// ======================= helpers =======================
__device__ __forceinline__ uint32_t smem_to_u32(const void* p) {
    uint32_t a;
    asm("{ .reg .u64 t; cvta.to.shared.u64 t, %1; cvt.u32.u64 %0, t; }" : "=r"(a) : "l"(p));
    return a;
}
__device__ __forceinline__ unsigned short bfbits(float v) {
    __nv_bfloat16 b = __float2bfloat16(v);
    return *reinterpret_cast<unsigned short*>(&b);
}
__device__ __forceinline__ float bfval(unsigned short u) {
    __nv_bfloat16 b = *reinterpret_cast<__nv_bfloat16*>(&u);
    return __bfloat162float(b);
}
__device__ __forceinline__ void ldm4(uint32_t* r, uint32_t addr) {
    asm volatile("ldmatrix.sync.aligned.m8n8.x4.shared.b16 {%0,%1,%2,%3}, [%4];"
                 : "=r"(r[0]), "=r"(r[1]), "=r"(r[2]), "=r"(r[3]) : "r"(addr));
}
__device__ __forceinline__ void mma16816(float* d, const uint32_t* a, const uint32_t* b) {
    asm volatile(
        "mma.sync.aligned.m16n8k16.row.col.f32.bf16.bf16.f32 "
        "{%0,%1,%2,%3}, {%4,%5,%6,%7}, {%8,%9}, {%0,%1,%2,%3};"
        : "+f"(d[0]), "+f"(d[1]), "+f"(d[2]), "+f"(d[3])
        : "r"(a[0]), "r"(a[1]), "r"(a[2]), "r"(a[3]), "r"(b[0]), "r"(b[1]));
}
__device__ __forceinline__ int edge_at(const void* ei, long long idx, int is64) {
    return is64 ? (int)((const long long*)ei)[idx] : ((const int*)ei)[idx];
}
__device__ __forceinline__ void cpa16(uint32_t dst, const void* src) {
    asm volatile("cp.async.cg.shared.global [%0], [%1], 16;" :: "r"(dst), "l"(src));
}
__device__ __forceinline__ void cpa16z(uint32_t dst, const void* src, int sz) {
    asm volatile("cp.async.cg.shared.global [%0], [%1], 16, %2;" :: "r"(dst), "l"(src), "r"(sz));
}
#define CPA_COMMIT() asm volatile("cp.async.commit_group;" ::: "memory")
#define CPA_WAIT0()  asm volatile("cp.async.wait_group 0;" ::: "memory")

// ---------------- K1: zero counters + barrier counter + dtype probe + W split ----------------
__global__ void init_kernel(const unsigned int* p, int n_vals, int N, const float* __restrict__ W) {
    int i = blockIdx.x * blockDim.x + threadIdx.x;
    if (i < N) g_cnt[i] = 0;
    if (i == 0) g_scnt = 0;
    if (blockIdx.x == 0) {
        __shared__ int any;
        int t = threadIdx.x;
        if (t == 0) any = 0;
        __syncthreads();
        int samples = n_vals < 512 ? n_vals : 512;
        for (int j = t; j < samples; j += blockDim.x)
            if (p[2 * j + 1] != 0u) any = 1;
        __syncthreads();
        if (t == 0) g_is64 = (any == 0) ? 1 : 0;
    }
    for (int k = i; k < COUT * CIN / 4; k += gridDim.x * blockDim.x) {
        float4 v = ((const float4*)W)[k];
        unsigned short h0 = bfbits(v.x), h1 = bfbits(v.y), h2 = bfbits(v.z), h3 = bfbits(v.w);
        unsigned short l0 = bfbits(v.x - bfval(h0)), l1 = bfbits(v.y - bfval(h1));
        unsigned short l2 = bfbits(v.z - bfval(h2)), l3 = bfbits(v.w - bfval(h3));
        uint2 hp, lp;
        hp.x = (uint32_t)h0 | ((uint32_t)h1 << 16); hp.y = (uint32_t)h2 | ((uint32_t)h3 << 16);
        lp.x = (uint32_t)l0 | ((uint32_t)l1 << 16); lp.y = (uint32_t)l2 | ((uint32_t)l3 << 16);
        ((uint2*)g_whi)[k] = hp;
        ((uint2*)g_wlo)[k] = lp;
    }
}

// ---------------- K2: degree histogram ----------------
__global__ void hist_kernel(const void* ei, int E) {
    int e = blockIdx.x * blockDim.x + threadIdx.x;
    if (e >= E) return;
    int dst = edge_at(ei, (long long)E + e, g_is64);
    atomicAdd(&g_cnt[dst], 1);
}

// ---------------- K3: merged scan (tile scan + device barrier + base add) ----------------
__global__ void scan_kernel(int N, int E) {
    __shared__ int sm[256];
    __shared__ int red[256];
    const int t = threadIdx.x, bid = blockIdx.x;
    const int i = bid * 256 + t;

    int v = (i < N) ? g_cnt[i] : 0;
    sm[t] = v;
    __syncthreads();
    for (int off = 1; off < 256; off <<= 1) {
        int add = (t >= off) ? sm[t - off] : 0;
        __syncthreads();
        sm[t] += add;
        __syncthreads();
    }
    int excl = sm[t] - v;                        // exclusive within block
    if (i < N) g_dinv[i] = rsqrtf((float)(v + 1));
    if (t == 255) g_bsum[bid] = sm[255];

    // device-wide barrier: publish tile sum, wait for all blocks
    __threadfence();
    __syncthreads();
    if (t == 0) {
        atomicAdd(&g_scnt, 1);
        while (*(volatile int*)&g_scnt < gridDim.x) { }
        __threadfence();
    }
    __syncthreads();

    // base = sum of earlier block sums
    int acc = 0;
    for (int j = t; j < bid; j += 256) acc += __ldcg(&g_bsum[j]);
    red[t] = acc;
    __syncthreads();
    for (int off = 128; off > 0; off >>= 1) {
        if (t < off) red[t] += red[t + off];
        __syncthreads();
    }
    int base = red[0];
    if (i < N) {
        int r = excl + base;
        g_rowptr[i] = r;
        g_cursor[i] = r;
        if (i == N - 1) g_rowptr[N] = r + v;
    }
}

// ---------------- K4: scatter edges into CSR records ----------------
__global__ void scatter_kernel(const void* ei, int E) {
    int e = blockIdx.x * blockDim.x + threadIdx.x;
    if (e >= E) return;
    int is64 = g_is64;
    int src = edge_at(ei, e, is64);
    int dst = edge_at(ei, (long long)E + e, is64);
    int pos = atomicAdd(&g_cursor[dst], 1);
    int2 r;
    r.x = src;
    r.y = __float_as_int(g_dinv[src]);
    g_rec[pos] = r;
}

// ---------------- aggregation inner (warp per dst, unroll x2) ----------------
__device__ __forceinline__ float4 agg_row(const float4* __restrict__ h4, int w, int lane) {
    float dd = g_dinv[w];
    float4 hv = h4[(size_t)w * 32 + lane];
    float s = dd * dd;
    float ax = s * hv.x, ay = s * hv.y, az = s * hv.z, aw = s * hv.w;
    float bx = 0.f, by = 0.f, bz = 0.f, bw = 0.f;
    int e = g_rowptr[w], end = g_rowptr[w + 1];
    for (; e + 2 <= end; e += 2) {
        int2 r0 = g_rec[e], r1 = g_rec[e + 1];
        float c0 = __int_as_float(r0.y) * dd;
        float c1 = __int_as_float(r1.y) * dd;
        float4 v0 = h4[(size_t)r0.x * 32 + lane];
        float4 v1 = h4[(size_t)r1.x * 32 + lane];
        ax += c0 * v0.x; ay += c0 * v0.y; az += c0 * v0.z; aw += c0 * v0.w;
        bx += c1 * v1.x; by += c1 * v1.y; bz += c1 * v1.z; bw += c1 * v1.w;
    }
    if (e < end) {
        int2 r0 = g_rec[e];
        float c0 = __int_as_float(r0.y) * dd;
        float4 v0 = h4[(size_t)r0.x * 32 + lane];
        ax += c0 * v0.x; ay += c0 * v0.y; az += c0 * v0.z; aw += c0 * v0.w;
    }
    float4 o;
    o.x = ax + bx; o.y = ay + by; o.z = az + bz; o.w = aw + bw;
    return o;
}

// K5: hop 1 -> f32
__global__ void agg_kernel(const float* __restrict__ hin, float* __restrict__ hout, int N) {
    int gt = blockIdx.x * blockDim.x + threadIdx.x;
    int w = gt >> 5, lane = gt & 31;
    if (w >= N) return;
    float4 o = agg_row((const float4*)hin, w, lane);
    ((float4*)hout)[(size_t)w * 32 + lane] = o;
}

// K6: hop 2 -> pre-split bf16 hi/lo
__global__ void agg_split_kernel(const float* __restrict__ hin, int N) {
    int gt = blockIdx.x * blockDim.x + threadIdx.x;
    int w = gt >> 5, lane = gt & 31;
    if (w >= N) return;
    float4 o = agg_row((const float4*)hin, w, lane);
    unsigned short h0 = bfbits(o.x), h1 = bfbits(o.y), h2 = bfbits(o.z), h3 = bfbits(o.w);
    unsigned short l0 = bfbits(o.x - bfval(h0)), l1 = bfbits(o.y - bfval(h1));
    unsigned short l2 = bfbits(o.z - bfval(h2)), l3 = bfbits(o.w - bfval(h3));
    uint2 hp, lp;
    hp.x = (uint32_t)h0 | ((uint32_t)h1 << 16); hp.y = (uint32_t)h2 | ((uint32_t)h3 << 16);
    lp.x = (uint32_t)l0 | ((uint32_t)l1 << 16); lp.y = (uint32_t)l2 | ((uint32_t)l3 << 16);
    ((uint2*)g_h1hi)[(size_t)w * 32 + lane] = hp;
    ((uint2*)g_h1lo)[(size_t)w * 32 + lane] = lp;
}

// ---------------- K7: mma.sync GEMM, 2 CTAs/SM, A-resident, 64-col steps,
//                  register-prefetched B (single smem buffer) ----------------
#define STRIDE_B 272
#define OFF_AHI  0
#define OFF_ALO  34816
#define OFF_BHI  69632
#define OFF_BLO  87040
#define MM_SMEM  104448

__global__ __launch_bounds__(256, 2) void mm_kernel(
    const float* __restrict__ bias, float* __restrict__ out, int N)
{
    extern __shared__ char smem[];
    const int tid = threadIdx.x;
    const int node0 = blockIdx.x * 128;
    const uint32_t sb = smem_to_u32(smem);

    const uint4* hhi = (const uint4*)g_h1hi;
    const uint4* hlo = (const uint4*)g_h1lo;
    const uint4* whi = (const uint4*)g_whi;
    const uint4* wlo = (const uint4*)g_wlo;

    // per-thread B-tile slots: 4 uint4 per plane
    const int prow = tid >> 4;               // 0..15 base row group? see mapping below
    // mapping: element i = tid + j*256 -> row=i>>4 (0..63), q=i&15
    // ---- prologue: issue A (zero-filled OOB) + B step 0 as one group ----
    for (int i = tid; i < 2048; i += 256) {
        int row = i >> 4, q = i & 15;
        int gn = node0 + row;
        int sz = (gn < N) ? 16 : 0;
        int gc = (gn < N) ? gn : 0;
        cpa16z(sb + OFF_AHI + row * STRIDE_B + q * 16, &hhi[(size_t)gc * 16 + q], sz);
        cpa16z(sb + OFF_ALO + row * STRIDE_B + q * 16, &hlo[(size_t)gc * 16 + q], sz);
    }
    for (int i = tid; i < 1024; i += 256) {
        int row = i >> 4, q = i & 15;                 // W rows 0..63
        cpa16(sb + OFF_BHI + row * STRIDE_B + q * 16, &whi[(size_t)row * 16 + q]);
        cpa16(sb + OFF_BLO + row * STRIDE_B + q * 16, &wlo[(size_t)row * 16 + q]);
    }
    CPA_COMMIT();
    (void)prow;

    const int lane = tid & 31, wid = tid >> 5;
    const int m0 = (wid & 3) * 32;          // 4 warps along M
    const int n0 = (wid >> 2) * 32;         // 2 warps along N (within 64-col step)

    const uint32_t aoff = (uint32_t)(m0 + (lane & 15)) * STRIDE_B + ((lane >> 4) << 4);
    const uint32_t boff = (uint32_t)(n0 + ((lane >> 4) << 3) + (lane & 7)) * STRIDE_B
                        + (((lane >> 3) & 1) << 4);
    const int g = lane >> 2, tg = lane & 3;

    const uint32_t aHiB = sb + OFF_AHI + aoff;
    const uint32_t aLoB = sb + OFF_ALO + aoff;
    const uint32_t bHiB = sb + OFF_BHI + boff;
    const uint32_t bLoB = sb + OFF_BLO + boff;

    CPA_WAIT0();
    __syncthreads();                         // A + B(0) ready

    for (int s = 0; s < 8; s++) {
        // register-prefetch B(s+1) while computing on B(s)
        uint4 pf[8];
        if (s < 7) {
            int colr0 = (s + 1) * 64;
            #pragma unroll
            for (int j = 0; j < 4; j++) {
                int i = tid + j * 256;
                int row = i >> 4, q = i & 15;
                pf[j]     = whi[(size_t)(colr0 + row) * 16 + q];
                pf[4 + j] = wlo[(size_t)(colr0 + row) * 16 + q];
            }
        }

        float acc[2][4][4];
        #pragma unroll
        for (int a = 0; a < 2; a++)
            #pragma unroll
            for (int b = 0; b < 4; b++)
                #pragma unroll
                for (int c = 0; c < 4; c++) acc[a][b][c] = 0.f;

        #pragma unroll
        for (int ks = 0; ks < 8; ks++) {
            uint32_t aH[2][4], aL[2][4], bH[4], bL[4];
            ldm4(aH[0], aHiB + ks * 32);
            ldm4(aH[1], aHiB + 16 * STRIDE_B + ks * 32);
            ldm4(aL[0], aLoB + ks * 32);
            ldm4(aL[1], aLoB + 16 * STRIDE_B + ks * 32);
            ldm4(bH, bHiB + ks * 32);
            ldm4(bL, bLoB + ks * 32);
            #pragma unroll
            for (int mt = 0; mt < 2; mt++) {
                mma16816(acc[mt][0], aH[mt], bH);
                mma16816(acc[mt][1], aH[mt], bH + 2);
                mma16816(acc[mt][0], aH[mt], bL);
                mma16816(acc[mt][1], aH[mt], bL + 2);
                mma16816(acc[mt][0], aL[mt], bH);
                mma16816(acc[mt][1], aL[mt], bH + 2);
            }
            uint32_t bH2[4], bL2[4];
            ldm4(bH2, bHiB + 16 * STRIDE_B + ks * 32);
            ldm4(bL2, bLoB + 16 * STRIDE_B + ks * 32);
            #pragma unroll
            for (int mt = 0; mt < 2; mt++) {
                mma16816(acc[mt][2], aH[mt], bH2);
                mma16816(acc[mt][3], aH[mt], bH2 + 2);
                mma16816(acc[mt][2], aH[mt], bL2);
                mma16816(acc[mt][3], aH[mt], bL2 + 2);
                mma16816(acc[mt][2], aL[mt], bH2);
                mma16816(acc[mt][3], aL[mt], bH2 + 2);
            }
        }
        __syncthreads();                     // all warps done reading B(s)

        if (s < 7) {
            // store prefetched B(s+1) into the (single) B buffer
            #pragma unroll
            for (int j = 0; j < 4; j++) {
                int i = tid + j * 256;
                int row = i >> 4, q = i & 15;
                *(uint4*)(smem + OFF_BHI + row * STRIDE_B + q * 16) = pf[j];
                *(uint4*)(smem + OFF_BLO + row * STRIDE_B + q * 16) = pf[4 + j];
            }
            __syncthreads();                 // B(s+1) visible to all warps
        }

        #pragma unroll
        for (int ng = 0; ng < 4; ng++) {
            int col = s * 64 + n0 + ng * 8 + tg * 2;
            float2 bb = *(const float2*)(bias + col);
            #pragma unroll
            for (int mt = 0; mt < 2; mt++) {
                int r0 = node0 + m0 + mt * 16 + g;
                if (r0 < N) {
                    float y0 = acc[mt][ng][0] + bb.x;
                    float y1 = acc[mt][ng][1] + bb.y;
                    float2 o;
                    o.x = (y0 >= 0.f) ? y0 : 0.1f * y0;
                    o.y = (y1 >= 0.f) ? y1 : 0.1f * y1;
                    *(float2*)(out + (size_t)r0 * COUT + col) = o;
                }
                int r1 = r0 + 8;
                if (r1 < N) {
                    float y2 = acc[mt][ng][2] + bb.x;
                    float y3 = acc[mt][ng][3] + bb.y;
                    float2 o;
                    o.x = (y2 >= 0.f) ? y2 : 0.1f * y2;
                    o.y = (y3 >= 0.f) ? y3 : 0.1f * y3;
                    *(float2*)(out + (size_t)r1 * COUT + col) = o;
                }
            }
        }
    }
}

extern "C" void kernel_launch(void* const* d_in, const int* in_sizes, int n_in,
                              void* d_out, int out_size) {
    const float* x  = (const float*)d_in[0];
    const void*  ei = d_in[1];
    const float* W  = (const float*)d_in[2];
    const float* b  = (const float*)d_in[3];
    float* out = (float*)d_out;

    int N = in_sizes[0] / CIN;
    int E = in_sizes[1] / 2;

    void* h0p = nullptr;
    cudaGetSymbolAddress(&h0p, g_h0);

    int nbN = (N + 255) / 256;
    int nbE = (E + 255) / 256;

    init_kernel<<<nbN, 256>>>((const unsigned int*)ei, 2 * E, N, W);
    hist_kernel<<<nbE, 256>>>(ei, E);
    scan_kernel<<<nbN, 256>>>(N, E);
    scatter_kernel<<<nbE, 256>>>(ei, E);

    int ab = (N * 32 + 255) / 256;
    agg_kernel<<<ab, 256>>>(x, (float*)h0p, N);
    agg_split_kernel<<<ab, 256>>>((const float*)h0p, N);

    cudaFuncSetAttribute(mm_kernel, cudaFuncAttributeMaxDynamicSharedMemorySize, MM_SMEM);
    mm_kernel<<<(N + 127) / 128, 256, MM_SMEM>>>(b, out, N);
}